// round 7
// baseline (speedup 1.0000x reference)
#include <cuda_runtime.h>
#include <cstdint>

#define N_MAX 100000
#define E_MAX 1600000
#define C 64
#define NEG_SLOPE 0.2f
#define EPS 1e-16f

// Scratch (no device allocation allowed)
__device__ float g_h[(size_t)N_MAX * C];
__device__ float g_out[(size_t)N_MAX * C];
__device__ float g_asrc[N_MAX];
__device__ float g_adst[N_MAX];
__device__ float g_e[E_MAX];
__device__ int   g_src[E_MAX];
__device__ int   g_dst[E_MAX];
__device__ float g_denom[N_MAX];
__device__ int   g_is64;

// 0) detect edge_index dtype: if the buffer is int64, every odd int32 word
//    (high half of each index) is zero; for int32 data they are random indices.
__global__ void kd_detect(const int* __restrict__ ei_raw) {
    __shared__ int nz[256];
    int t = threadIdx.x;
    int acc = 0;
    for (int k = t; k < 2048; k += 256) acc |= ei_raw[2 * k + 1];
    nz[t] = acc;
    __syncthreads();
    for (int s = 128; s > 0; s >>= 1) {
        if (t < s) nz[t] |= nz[t + s];
        __syncthreads();
    }
    if (t == 0) g_is64 = (nz[0] == 0) ? 1 : 0;
}

// 1) init: zero accumulator + denom
__global__ void kc_init(int N) {
    int total = N * C;
    for (int i = blockIdx.x * blockDim.x + threadIdx.x; i < total;
         i += gridDim.x * blockDim.x) {
        g_out[i] = 0.0f;
        if (i < N) g_denom[i] = 0.0f;
    }
}

// 2) h = x @ W ; a_src = h.att_src ; a_dst = h.att_dst  (no atomics)
__global__ __launch_bounds__(256) void kc_gemm(
    const float* __restrict__ x, const float* __restrict__ W,
    const float* __restrict__ att_src, const float* __restrict__ att_dst,
    int N)
{
    __shared__ float Ws[C * C];       // 16 KB
    __shared__ float xs[32 * C];      // 8 KB
    __shared__ float part[32][2][2];  // [row][half][src/dst]
    int tid  = threadIdx.x;
    int lane = tid & 31;
    int half = (tid >> 5) & 1;
    int rq   = tid >> 6;
    int col  = half * 32 + lane;

    for (int i = tid; i < C * C; i += 256) Ws[i] = W[i];
    int row0 = blockIdx.x * 32;
    int nrows = min(32, N - row0);
    if (nrows <= 0) return;
    for (int i = tid; i < nrows * C; i += 256) xs[i] = x[(size_t)row0 * C + i];
    __syncthreads();

    float as = att_src[col];
    float ad = att_dst[col];
    for (int r = rq; r < nrows; r += 4) {
        float acc = 0.0f;
        #pragma unroll
        for (int k = 0; k < C; k++)
            acc = fmaf(xs[r * C + k], Ws[k * C + col], acc);
        g_h[(size_t)(row0 + r) * C + col] = acc;
        float ps = acc * as;
        float pd = acc * ad;
        #pragma unroll
        for (int off = 16; off > 0; off >>= 1) {
            ps += __shfl_down_sync(0xffffffffu, ps, off);
            pd += __shfl_down_sync(0xffffffffu, pd, off);
        }
        if (lane == 0) { part[r][half][0] = ps; part[r][half][1] = pd; }
    }
    __syncthreads();
    if (tid < nrows) {
        g_asrc[row0 + tid] = part[tid][0][0] + part[tid][1][0];
        g_adst[row0 + tid] = part[tid][0][1] + part[tid][1][1];
    }
}

// 3) per-edge: idx load (dtype-flag branch) + clamp, leaky_relu logit,
//    exp (unshifted — softmax is shift-invariant, logits are O(10)), denom sum
__global__ __launch_bounds__(256) void kc_edge(
    const int* __restrict__ ei, int E, int N)
{
    const long long* el = (const long long*)ei;
    int is64 = g_is64;
    for (int i = blockIdx.x * blockDim.x + threadIdx.x; i < E;
         i += gridDim.x * blockDim.x) {
        int s, d;
        if (is64) { s = (int)el[i]; d = (int)el[E + i]; }
        else      { s = ei[i];      d = ei[E + i]; }
        s = ((unsigned)s < (unsigned)N) ? s : 0;
        d = ((unsigned)d < (unsigned)N) ? d : 0;
        g_src[i] = s;
        g_dst[i] = d;
        float v = g_asrc[s] + g_adst[d];
        v = (v > 0.0f) ? v : NEG_SLOPE * v;
        float ex = __expf(v);
        g_e[i] = ex;
        atomicAdd(&g_denom[d], ex);
    }
}

// 4) scatter: g_out[dst] += alpha * h[src]
//    16 threads/edge: each loads one float4 of h[src], does 4 scalar atomicAdds.
__global__ __launch_bounds__(256) void kc_scat(int E)
{
    long long total = (long long)E * 16;
    for (long long g = blockIdx.x * (long long)blockDim.x + threadIdx.x;
         g < total; g += (long long)gridDim.x * blockDim.x) {
        int e    = (int)(g >> 4);
        int part = (int)(g & 15);
        int s = g_src[e];
        int d = g_dst[e];
        float alpha = g_e[e] / (g_denom[d] + EPS);
        float4 hv = *(const float4*)&g_h[(size_t)s * C + part * 4];
        float* po = &g_out[(size_t)d * C + part * 4];
        atomicAdd(po + 0, alpha * hv.x);
        atomicAdd(po + 1, alpha * hv.y);
        atomicAdd(po + 2, alpha * hv.z);
        atomicAdd(po + 3, alpha * hv.w);
    }
}

// 5) out = tanh(g_out + bias)  (plain vectorized stores to d_out only)
__global__ __launch_bounds__(256) void kc_tanh(
    float* __restrict__ out, const float* __restrict__ bias, int N)
{
    int total4 = N * C / 4;
    for (int i = blockIdx.x * blockDim.x + threadIdx.x; i < total4;
         i += gridDim.x * blockDim.x) {
        float4 v = *(const float4*)&g_out[(size_t)i * 4];
        int cb = (i * 4) & 63;
        v.x = tanhf(v.x + bias[cb + 0]);
        v.y = tanhf(v.y + bias[cb + 1]);
        v.z = tanhf(v.z + bias[cb + 2]);
        v.w = tanhf(v.w + bias[cb + 3]);
        *(float4*)&out[(size_t)i * 4] = v;
    }
}

extern "C" void kernel_launch(void* const* d_in, const int* in_sizes, int n_in,
                              void* d_out, int out_size)
{
    const float* x       = (const float*)d_in[0];
    const int*   ei      = (const int*)d_in[1];
    const float* W       = (const float*)d_in[2];
    const float* att_src = (const float*)d_in[3];
    const float* att_dst = (const float*)d_in[4];
    const float* bias    = (const float*)d_in[5];
    float* out = (float*)d_out;

    int N = in_sizes[0] / C;
    int E = in_sizes[1] / 2;

    int gridN64 = (N * C + 255) / 256;
    int gridN16 = (N * C / 4 + 255) / 256;
    int gridE   = (E + 255) / 256;
    long long scatter_threads = (long long)E * 16;
    int gridS = (int)((scatter_threads + 255) / 256);

    kd_detect<<<1, 256>>>(ei);
    kc_init<<<gridN64, 256>>>(N);
    kc_gemm<<<(N + 31) / 32, 256>>>(x, W, att_src, att_dst, N);
    kc_edge<<<gridE, 256>>>(ei, E, N);
    kc_scat<<<gridS, 256>>>(E);
    kc_tanh<<<gridN16, 256>>>(out, bias, N);
}

// round 8
// speedup vs baseline: 1.0832x; 1.0832x over previous
#include <cuda_runtime.h>
#include <cstdint>

#define N_MAX 100000
#define E_MAX 1600000
#define C 64
#define NEG_SLOPE 0.2f
#define EPS 1e-16f

// Scratch (no device allocation allowed)
__device__ float g_h[(size_t)N_MAX * C];
__device__ float g_asrc[N_MAX];
__device__ float g_adst[N_MAX];
__device__ int2  g_se[E_MAX];      // sorted-by-dst: {src, e_bits}
__device__ int   g_cnt[N_MAX];     // histogram, then fill cursor, then count again
__device__ int   g_off[N_MAX];     // exclusive prefix offsets
__device__ int   g_is64;

// 0) detect edge_index dtype (int32 vs int64 buffer)
__global__ void kf_detect(const int* __restrict__ ei_raw) {
    __shared__ int nz[256];
    int t = threadIdx.x;
    int acc = 0;
    for (int k = t; k < 2048; k += 256) acc |= ei_raw[2 * k + 1];
    nz[t] = acc;
    __syncthreads();
    for (int s = 128; s > 0; s >>= 1) {
        if (t < s) nz[t] |= nz[t + s];
        __syncthreads();
    }
    if (t == 0) g_is64 = (nz[0] == 0) ? 1 : 0;
}

// 1) zero counts
__global__ void kf_zero(int N) {
    for (int i = blockIdx.x * blockDim.x + threadIdx.x; i < N;
         i += gridDim.x * blockDim.x)
        g_cnt[i] = 0;
}

// 2) histogram of dst
__global__ __launch_bounds__(256) void kf_hist(
    const int* __restrict__ ei, int E, int N)
{
    const long long* el = (const long long*)ei;
    int is64 = g_is64;
    for (int i = blockIdx.x * blockDim.x + threadIdx.x; i < E;
         i += gridDim.x * blockDim.x) {
        int d = is64 ? (int)el[E + i] : ei[E + i];
        d = ((unsigned)d < (unsigned)N) ? d : 0;
        atomicAdd(&g_cnt[d], 1);
    }
}

// 3) exclusive prefix scan (1 block, 1024 threads); resets g_cnt to 0
__global__ __launch_bounds__(1024) void kf_scan(int N) {
    __shared__ int ssum[1024];
    int t = threadIdx.x;
    int chunk = (N + 1023) / 1024;
    int lo = t * chunk, hi = min(lo + chunk, N);
    int s = 0;
    for (int i = lo; i < hi; i++) s += g_cnt[i];
    ssum[t] = s;
    __syncthreads();
    for (int off = 1; off < 1024; off <<= 1) {
        int v = (t >= off) ? ssum[t - off] : 0;
        __syncthreads();
        ssum[t] += v;
        __syncthreads();
    }
    int excl = (t == 0) ? 0 : ssum[t - 1];
    for (int i = lo; i < hi; i++) {
        int c = g_cnt[i];
        g_off[i] = excl;
        g_cnt[i] = 0;          // becomes fill cursor for reorder
        excl += c;
    }
}

// 4) h = x @ W ; a_src/a_dst logits (no atomics)
__global__ __launch_bounds__(256) void kf_gemm(
    const float* __restrict__ x, const float* __restrict__ W,
    const float* __restrict__ att_src, const float* __restrict__ att_dst,
    int N)
{
    __shared__ float Ws[C * C];
    __shared__ float xs[32 * C];
    __shared__ float part[32][2][2];
    int tid  = threadIdx.x;
    int lane = tid & 31;
    int half = (tid >> 5) & 1;
    int rq   = tid >> 6;
    int col  = half * 32 + lane;

    for (int i = tid; i < C * C; i += 256) Ws[i] = W[i];
    int row0 = blockIdx.x * 32;
    int nrows = min(32, N - row0);
    if (nrows <= 0) return;
    for (int i = tid; i < nrows * C; i += 256) xs[i] = x[(size_t)row0 * C + i];
    __syncthreads();

    float as = att_src[col];
    float ad = att_dst[col];
    for (int r = rq; r < nrows; r += 4) {
        float acc = 0.0f;
        #pragma unroll
        for (int k = 0; k < C; k++)
            acc = fmaf(xs[r * C + k], Ws[k * C + col], acc);
        g_h[(size_t)(row0 + r) * C + col] = acc;
        float ps = acc * as;
        float pd = acc * ad;
        #pragma unroll
        for (int off = 16; off > 0; off >>= 1) {
            ps += __shfl_down_sync(0xffffffffu, ps, off);
            pd += __shfl_down_sync(0xffffffffu, pd, off);
        }
        if (lane == 0) { part[r][half][0] = ps; part[r][half][1] = pd; }
    }
    __syncthreads();
    if (tid < nrows) {
        g_asrc[row0 + tid] = part[tid][0][0] + part[tid][1][0];
        g_adst[row0 + tid] = part[tid][0][1] + part[tid][1][1];
    }
}

// 5) per-edge: logit -> exp (unshifted; shift-invariant softmax, logits O(10)),
//    claim sorted slot, write packed {src, e_bits}
__global__ __launch_bounds__(256) void kf_edge_reorder(
    const int* __restrict__ ei, int E, int N)
{
    const long long* el = (const long long*)ei;
    int is64 = g_is64;
    for (int i = blockIdx.x * blockDim.x + threadIdx.x; i < E;
         i += gridDim.x * blockDim.x) {
        int s, d;
        if (is64) { s = (int)el[i]; d = (int)el[E + i]; }
        else      { s = ei[i];      d = ei[E + i]; }
        s = ((unsigned)s < (unsigned)N) ? s : 0;
        d = ((unsigned)d < (unsigned)N) ? d : 0;
        float v = g_asrc[s] + g_adst[d];
        v = (v > 0.0f) ? v : NEG_SLOPE * v;
        float ex = __expf(v);
        int p = g_off[d] + atomicAdd(&g_cnt[d], 1);
        g_se[p] = make_int2(s, __float_as_int(ex));
    }
}

// 6) gather: one warp per dst node; denom + weighted sum + tanh(+bias) -> out
__global__ __launch_bounds__(256) void kf_gather(
    float* __restrict__ out, const float* __restrict__ bias, int N)
{
    int warp = (blockIdx.x * blockDim.x + threadIdx.x) >> 5;
    int lane = threadIdx.x & 31;
    if (warp >= N) return;
    int beg = g_off[warp];
    int end = beg + g_cnt[warp];   // cnt restored to degree by reorder

    // denominator
    float ds = 0.0f;
    for (int j = beg + lane; j < end; j += 32)
        ds += __int_as_float(g_se[j].y);
    #pragma unroll
    for (int o = 16; o > 0; o >>= 1)
        ds += __shfl_xor_sync(0xffffffffu, ds, o);
    float inv = 1.0f / (ds + EPS);

    // weighted feature sum: each lane owns 2 channels (float2 of the 64-wide row)
    float2 acc = make_float2(0.0f, 0.0f);
    for (int j = beg; j < end; j++) {
        int2 se = g_se[j];                       // broadcast load
        float a = __int_as_float(se.y) * inv;
        float2 hv = *(const float2*)&g_h[(size_t)se.x * C + lane * 2];
        acc.x = fmaf(a, hv.x, acc.x);
        acc.y = fmaf(a, hv.y, acc.y);
    }
    float2 r;
    r.x = tanhf(acc.x + bias[lane * 2 + 0]);
    r.y = tanhf(acc.y + bias[lane * 2 + 1]);
    *(float2*)&out[(size_t)warp * C + lane * 2] = r;
}

extern "C" void kernel_launch(void* const* d_in, const int* in_sizes, int n_in,
                              void* d_out, int out_size)
{
    const float* x       = (const float*)d_in[0];
    const int*   ei      = (const int*)d_in[1];
    const float* W       = (const float*)d_in[2];
    const float* att_src = (const float*)d_in[3];
    const float* att_dst = (const float*)d_in[4];
    const float* bias    = (const float*)d_in[5];
    float* out = (float*)d_out;

    int N = in_sizes[0] / C;
    int E = in_sizes[1] / 2;

    int gridE = (E + 255) / 256;
    int gridN = (N + 255) / 256;

    kf_detect<<<1, 256>>>(ei);
    kf_zero<<<gridN, 256>>>(N);
    kf_hist<<<gridE, 256>>>(ei, E, N);
    kf_scan<<<1, 1024>>>(N);
    kf_gemm<<<(N + 31) / 32, 256>>>(x, W, att_src, att_dst, N);
    kf_edge_reorder<<<gridE, 256>>>(ei, E, N);
    kf_gather<<<(N * 32 + 255) / 256, 256>>>(out, bias, N);
}

// round 10
// speedup vs baseline: 1.9886x; 1.8358x over previous
#include <cuda_runtime.h>
#include <cstdint>

#define N_MAX 100000
#define E_MAX 1600000
#define C 64
#define NEG_SLOPE 0.2f
#define EPS 1e-16f
#define SCHUNK 1024                      // counts per scan block
#define NB_MAX ((N_MAX + SCHUNK - 1) / SCHUNK)

// Scratch (no device allocation allowed)
__device__ float g_h[(size_t)N_MAX * C];
__device__ float g_asrc[N_MAX];
__device__ float g_adst[N_MAX];
__device__ int2  g_se[E_MAX];            // sorted-by-dst: {src, e_bits}
__device__ int   g_cnt[N_MAX];           // histogram -> fill cursor -> degree
__device__ int   g_off[N_MAX];           // exclusive prefix offsets
__device__ int   g_bsum[1024];           // per-block sums for scan
__device__ int   g_is64;

// 0) detect edge_index dtype (int32 vs int64 buffer)
__global__ void kf_detect(const int* __restrict__ ei_raw) {
    __shared__ int nz[256];
    int t = threadIdx.x;
    int acc = 0;
    for (int k = t; k < 2048; k += 256) acc |= ei_raw[2 * k + 1];
    nz[t] = acc;
    __syncthreads();
    for (int s = 128; s > 0; s >>= 1) {
        if (t < s) nz[t] |= nz[t + s];
        __syncthreads();
    }
    if (t == 0) g_is64 = (nz[0] == 0) ? 1 : 0;
}

// 1) zero counts
__global__ void kf_zero(int N) {
    for (int i = blockIdx.x * blockDim.x + threadIdx.x; i < N;
         i += gridDim.x * blockDim.x)
        g_cnt[i] = 0;
}

// 2) histogram of dst
__global__ __launch_bounds__(256) void kf_hist(
    const int* __restrict__ ei, int E, int N)
{
    const long long* el = (const long long*)ei;
    int is64 = g_is64;
    for (int i = blockIdx.x * blockDim.x + threadIdx.x; i < E;
         i += gridDim.x * blockDim.x) {
        int d = is64 ? (int)el[E + i] : ei[E + i];
        d = ((unsigned)d < (unsigned)N) ? d : 0;
        atomicAdd(&g_cnt[d], 1);
    }
}

// 3a) per-block sums of counts (4 counts/thread)
__global__ __launch_bounds__(256) void kf_scanA(int N) {
    __shared__ int sh[256];
    int t = threadIdx.x;
    int base = blockIdx.x * SCHUNK + t * 4;
    int s = 0;
    #pragma unroll
    for (int k = 0; k < 4; k++) {
        int i = base + k;
        if (i < N) s += g_cnt[i];
    }
    sh[t] = s;
    __syncthreads();
    for (int o = 128; o > 0; o >>= 1) {
        if (t < o) sh[t] += sh[t + o];
        __syncthreads();
    }
    if (t == 0) g_bsum[blockIdx.x] = sh[0];
}

// 3b) exclusive scan of block sums (one block)
__global__ __launch_bounds__(1024) void kf_scanB(int NB) {
    __shared__ int sh[1024];
    int t = threadIdx.x;
    int v = (t < NB) ? g_bsum[t] : 0;
    sh[t] = v;
    __syncthreads();
    for (int o = 1; o < 1024; o <<= 1) {
        int u = (t >= o) ? sh[t - o] : 0;
        __syncthreads();
        sh[t] += u;
        __syncthreads();
    }
    if (t < NB) g_bsum[t] = sh[t] - v;   // exclusive
}

// 3c) intra-block exclusive scan + global offset; writes g_off, zeroes g_cnt
__global__ __launch_bounds__(256) void kf_scanC(int N) {
    __shared__ int sh[256];
    int t = threadIdx.x;
    int base = blockIdx.x * SCHUNK + t * 4;
    int c[4];
    int s = 0;
    #pragma unroll
    for (int k = 0; k < 4; k++) {
        int i = base + k;
        c[k] = (i < N) ? g_cnt[i] : 0;
        s += c[k];
    }
    sh[t] = s;
    __syncthreads();
    for (int o = 1; o < 256; o <<= 1) {
        int u = (t >= o) ? sh[t - o] : 0;
        __syncthreads();
        sh[t] += u;
        __syncthreads();
    }
    int excl = g_bsum[blockIdx.x] + sh[t] - s;   // exclusive thread offset
    #pragma unroll
    for (int k = 0; k < 4; k++) {
        int i = base + k;
        if (i < N) {
            g_off[i] = excl;
            g_cnt[i] = 0;                        // fill cursor for reorder
            excl += c[k];
        }
    }
}

// 4) h = x @ W ; a_src/a_dst logits (no atomics)
__global__ __launch_bounds__(256) void kf_gemm(
    const float* __restrict__ x, const float* __restrict__ W,
    const float* __restrict__ att_src, const float* __restrict__ att_dst,
    int N)
{
    __shared__ float Ws[C * C];
    __shared__ float xs[32 * C];
    __shared__ float part[32][2][2];
    int tid  = threadIdx.x;
    int lane = tid & 31;
    int half = (tid >> 5) & 1;
    int rq   = tid >> 6;
    int col  = half * 32 + lane;

    for (int i = tid; i < C * C; i += 256) Ws[i] = W[i];
    int row0 = blockIdx.x * 32;
    int nrows = min(32, N - row0);
    if (nrows <= 0) return;
    for (int i = tid; i < nrows * C; i += 256) xs[i] = x[(size_t)row0 * C + i];
    __syncthreads();

    float as = att_src[col];
    float ad = att_dst[col];
    for (int r = rq; r < nrows; r += 4) {
        float acc = 0.0f;
        #pragma unroll
        for (int k = 0; k < C; k++)
            acc = fmaf(xs[r * C + k], Ws[k * C + col], acc);
        g_h[(size_t)(row0 + r) * C + col] = acc;
        float ps = acc * as;
        float pd = acc * ad;
        #pragma unroll
        for (int off = 16; off > 0; off >>= 1) {
            ps += __shfl_down_sync(0xffffffffu, ps, off);
            pd += __shfl_down_sync(0xffffffffu, pd, off);
        }
        if (lane == 0) { part[r][half][0] = ps; part[r][half][1] = pd; }
    }
    __syncthreads();
    if (tid < nrows) {
        g_asrc[row0 + tid] = part[tid][0][0] + part[tid][1][0];
        g_adst[row0 + tid] = part[tid][0][1] + part[tid][1][1];
    }
}

// 5) per-edge: logit -> exp (unshifted; softmax shift-invariant, logits O(10)),
//    claim sorted slot, write packed {src, e_bits}
__global__ __launch_bounds__(256) void kf_edge_reorder(
    const int* __restrict__ ei, int E, int N)
{
    const long long* el = (const long long*)ei;
    int is64 = g_is64;
    for (int i = blockIdx.x * blockDim.x + threadIdx.x; i < E;
         i += gridDim.x * blockDim.x) {
        int s, d;
        if (is64) { s = (int)el[i]; d = (int)el[E + i]; }
        else      { s = ei[i];      d = ei[E + i]; }
        s = ((unsigned)s < (unsigned)N) ? s : 0;
        d = ((unsigned)d < (unsigned)N) ? d : 0;
        float v = g_asrc[s] + g_adst[d];
        v = (v > 0.0f) ? v : NEG_SLOPE * v;
        float ex = __expf(v);
        int p = g_off[d] + atomicAdd(&g_cnt[d], 1);
        g_se[p] = make_int2(s, __float_as_int(ex));
    }
}

// 6) gather: one warp per dst node; denom + weighted sum + tanh(+bias) -> out
__global__ __launch_bounds__(256) void kf_gather(
    float* __restrict__ out, const float* __restrict__ bias, int N)
{
    int warp = (blockIdx.x * blockDim.x + threadIdx.x) >> 5;
    int lane = threadIdx.x & 31;
    if (warp >= N) return;
    int beg = g_off[warp];
    int deg = g_cnt[warp];         // cnt restored to degree by reorder
    int end = beg + deg;

    // denominator
    float ds = 0.0f;
    for (int j = beg + lane; j < end; j += 32)
        ds += __int_as_float(g_se[j].y);
    #pragma unroll
    for (int o = 16; o > 0; o >>= 1)
        ds += __shfl_xor_sync(0xffffffffu, ds, o);
    float inv = 1.0f / (ds + EPS);

    // weighted feature sum: each lane owns 2 channels (float2 of the 64-wide row)
    float2 acc = make_float2(0.0f, 0.0f);
    int j = beg;
    // two edges per iteration when 16B-aligned (g_se is int2 = 8B; beg even => aligned)
    if ((beg & 1) == 0) {
        for (; j + 1 < end; j += 2) {
            int4 p2 = *(const int4*)&g_se[j];    // {s0, e0, s1, e1} broadcast
            float a0 = __int_as_float(p2.y) * inv;
            float a1 = __int_as_float(p2.w) * inv;
            float2 h0 = *(const float2*)&g_h[(size_t)p2.x * C + lane * 2];
            float2 h1 = *(const float2*)&g_h[(size_t)p2.z * C + lane * 2];
            acc.x = fmaf(a0, h0.x, acc.x);
            acc.y = fmaf(a0, h0.y, acc.y);
            acc.x = fmaf(a1, h1.x, acc.x);
            acc.y = fmaf(a1, h1.y, acc.y);
        }
    }
    for (; j < end; j++) {
        int2 se = g_se[j];
        float a = __int_as_float(se.y) * inv;
        float2 hv = *(const float2*)&g_h[(size_t)se.x * C + lane * 2];
        acc.x = fmaf(a, hv.x, acc.x);
        acc.y = fmaf(a, hv.y, acc.y);
    }
    float2 r;
    r.x = tanhf(acc.x + bias[lane * 2 + 0]);
    r.y = tanhf(acc.y + bias[lane * 2 + 1]);
    *(float2*)&out[(size_t)warp * C + lane * 2] = r;
}

extern "C" void kernel_launch(void* const* d_in, const int* in_sizes, int n_in,
                              void* d_out, int out_size)
{
    const float* x       = (const float*)d_in[0];
    const int*   ei      = (const int*)d_in[1];
    const float* W       = (const float*)d_in[2];
    const float* att_src = (const float*)d_in[3];
    const float* att_dst = (const float*)d_in[4];
    const float* bias    = (const float*)d_in[5];
    float* out = (float*)d_out;

    int N = in_sizes[0] / C;
    int E = in_sizes[1] / 2;

    int gridE = (E + 255) / 256;
    int gridN = (N + 255) / 256;
    int NB = (N + SCHUNK - 1) / SCHUNK;

    kf_detect<<<1, 256>>>(ei);
    kf_zero<<<gridN, 256>>>(N);
    kf_hist<<<gridE, 256>>>(ei, E, N);
    kf_scanA<<<NB, 256>>>(N);
    kf_scanB<<<1, 1024>>>(NB);
    kf_scanC<<<NB, 256>>>(N);
    kf_gemm<<<(N + 31) / 32, 256>>>(x, W, att_src, att_dst, N);
    kf_edge_reorder<<<gridE, 256>>>(ei, E, N);
    kf_gather<<<(N * 32 + 255) / 256, 256>>>(out, bias, N);
}

// round 12
// speedup vs baseline: 2.0119x; 1.0117x over previous
#include <cuda_runtime.h>
#include <cuda_fp16.h>
#include <cstdint>

#define N_MAX 100000
#define E_MAX 1600000
#define C 64
#define NEG_SLOPE 0.2f
#define EPS 1e-16f
#define SCHUNK 1024

// Scratch (no device allocation allowed)
__device__ __half2 gv_h2[(size_t)N_MAX * (C / 2)];   // h in fp16 (gather-only consumer)
__device__ float   gv_asrc[N_MAX];
__device__ float   gv_adst[N_MAX];
__device__ int2    gv_se[E_MAX];          // sorted-by-dst: {src, e_bits}
__device__ int     gv_cnt[N_MAX];         // histogram -> fill cursor -> degree
__device__ int     gv_off[N_MAX];         // exclusive prefix offsets
__device__ float   gv_denom[N_MAX];
__device__ int     gv_bsum[1024];
__device__ int     gv_is64;

// 0) detect edge_index dtype (int32 vs int64 buffer)
__global__ void kh_detect(const int* __restrict__ ei_raw) {
    __shared__ int nz[256];
    int t = threadIdx.x;
    int acc = 0;
    for (int k = t; k < 2048; k += 256) acc |= ei_raw[2 * k + 1];
    nz[t] = acc;
    __syncthreads();
    for (int s = 128; s > 0; s >>= 1) {
        if (t < s) nz[t] |= nz[t + s];
        __syncthreads();
    }
    if (t == 0) gv_is64 = (nz[0] == 0) ? 1 : 0;
}

// 1) zero counts + denom
__global__ void kh_zero(int N) {
    for (int i = blockIdx.x * blockDim.x + threadIdx.x; i < N;
         i += gridDim.x * blockDim.x) {
        gv_cnt[i] = 0;
        gv_denom[i] = 0.0f;
    }
}

// 2) histogram of dst (int4-vectorized: 4 edges/thread)
__global__ __launch_bounds__(256) void kh_hist(
    const int* __restrict__ ei, int E, int N)
{
    const long long* el = (const long long*)ei;
    int is64 = gv_is64;
    if (!is64) {
        const int4* dst4 = (const int4*)(ei + E);
        int E4 = E >> 2;
        for (int i = blockIdx.x * blockDim.x + threadIdx.x; i < E4;
             i += gridDim.x * blockDim.x) {
            int4 d4 = dst4[i];
            int d0 = ((unsigned)d4.x < (unsigned)N) ? d4.x : 0;
            int d1 = ((unsigned)d4.y < (unsigned)N) ? d4.y : 0;
            int d2 = ((unsigned)d4.z < (unsigned)N) ? d4.z : 0;
            int d3 = ((unsigned)d4.w < (unsigned)N) ? d4.w : 0;
            atomicAdd(&gv_cnt[d0], 1);
            atomicAdd(&gv_cnt[d1], 1);
            atomicAdd(&gv_cnt[d2], 1);
            atomicAdd(&gv_cnt[d3], 1);
        }
        for (int i = (E4 << 2) + blockIdx.x * blockDim.x + threadIdx.x; i < E;
             i += gridDim.x * blockDim.x) {
            int d = ei[E + i];
            d = ((unsigned)d < (unsigned)N) ? d : 0;
            atomicAdd(&gv_cnt[d], 1);
        }
    } else {
        for (int i = blockIdx.x * blockDim.x + threadIdx.x; i < E;
             i += gridDim.x * blockDim.x) {
            int d = (int)el[E + i];
            d = ((unsigned)d < (unsigned)N) ? d : 0;
            atomicAdd(&gv_cnt[d], 1);
        }
    }
}

// 3a) per-block sums of counts
__global__ __launch_bounds__(256) void kh_scanA(int N) {
    __shared__ int sh[256];
    int t = threadIdx.x;
    int base = blockIdx.x * SCHUNK + t * 4;
    int s = 0;
    #pragma unroll
    for (int k = 0; k < 4; k++) {
        int i = base + k;
        if (i < N) s += gv_cnt[i];
    }
    sh[t] = s;
    __syncthreads();
    for (int o = 128; o > 0; o >>= 1) {
        if (t < o) sh[t] += sh[t + o];
        __syncthreads();
    }
    if (t == 0) gv_bsum[blockIdx.x] = sh[0];
}

// 3b) exclusive scan of block sums
__global__ __launch_bounds__(1024) void kh_scanB(int NB) {
    __shared__ int sh[1024];
    int t = threadIdx.x;
    int v = (t < NB) ? gv_bsum[t] : 0;
    sh[t] = v;
    __syncthreads();
    for (int o = 1; o < 1024; o <<= 1) {
        int u = (t >= o) ? sh[t - o] : 0;
        __syncthreads();
        sh[t] += u;
        __syncthreads();
    }
    if (t < NB) gv_bsum[t] = sh[t] - v;
}

// 3c) intra-block exclusive scan; writes gv_off, zeroes gv_cnt (fill cursor)
__global__ __launch_bounds__(256) void kh_scanC(int N) {
    __shared__ int sh[256];
    int t = threadIdx.x;
    int base = blockIdx.x * SCHUNK + t * 4;
    int c[4];
    int s = 0;
    #pragma unroll
    for (int k = 0; k < 4; k++) {
        int i = base + k;
        c[k] = (i < N) ? gv_cnt[i] : 0;
        s += c[k];
    }
    sh[t] = s;
    __syncthreads();
    for (int o = 1; o < 256; o <<= 1) {
        int u = (t >= o) ? sh[t - o] : 0;
        __syncthreads();
        sh[t] += u;
        __syncthreads();
    }
    int excl = gv_bsum[blockIdx.x] + sh[t] - s;
    #pragma unroll
    for (int k = 0; k < 4; k++) {
        int i = base + k;
        if (i < N) {
            gv_off[i] = excl;
            gv_cnt[i] = 0;
            excl += c[k];
        }
    }
}

// 4) h = x @ W (fp32 compute, fp16 store); a_src/a_dst logits fp32
__global__ __launch_bounds__(256) void kh_gemm(
    const float* __restrict__ x, const float* __restrict__ W,
    const float* __restrict__ att_src, const float* __restrict__ att_dst,
    int N)
{
    __shared__ float Ws[C * C];
    __shared__ float xs[32 * C];
    __shared__ float part[32][2][2];
    int tid  = threadIdx.x;
    int lane = tid & 31;
    int half = (tid >> 5) & 1;
    int rq   = tid >> 6;
    int col  = half * 32 + lane;

    for (int i = tid; i < C * C; i += 256) Ws[i] = W[i];
    int row0 = blockIdx.x * 32;
    int nrows = min(32, N - row0);
    if (nrows <= 0) return;
    for (int i = tid; i < nrows * C; i += 256) xs[i] = x[(size_t)row0 * C + i];
    __syncthreads();

    float as = att_src[col];
    float ad = att_dst[col];
    for (int r = rq; r < nrows; r += 4) {
        float acc = 0.0f;
        #pragma unroll
        for (int k = 0; k < C; k++)
            acc = fmaf(xs[r * C + k], Ws[k * C + col], acc);
        // pack two adjacent columns into one half2 (even lanes write)
        float nb = __shfl_down_sync(0xffffffffu, acc, 1);
        if ((lane & 1) == 0)
            gv_h2[(size_t)(row0 + r) * (C / 2) + (col >> 1)] =
                __floats2half2_rn(acc, nb);
        float ps = acc * as;
        float pd = acc * ad;
        #pragma unroll
        for (int off = 16; off > 0; off >>= 1) {
            ps += __shfl_down_sync(0xffffffffu, ps, off);
            pd += __shfl_down_sync(0xffffffffu, pd, off);
        }
        if (lane == 0) { part[r][half][0] = ps; part[r][half][1] = pd; }
    }
    __syncthreads();
    if (tid < nrows) {
        gv_asrc[row0 + tid] = part[tid][0][0] + part[tid][1][0];
        gv_adst[row0 + tid] = part[tid][0][1] + part[tid][1][1];
    }
}

// 5) per-edge: logit -> exp, denom atomicAdd, claim sorted slot, write {src,e}
__global__ __launch_bounds__(256) void kh_reorder(
    const int* __restrict__ ei, int E, int N)
{
    int is64 = gv_is64;
    if (!is64) {
        const int4* src4 = (const int4*)ei;
        const int4* dst4 = (const int4*)(ei + E);
        int E4 = E >> 2;
        for (int i = blockIdx.x * blockDim.x + threadIdx.x; i < E4;
             i += gridDim.x * blockDim.x) {
            int4 s4 = src4[i];
            int4 d4 = dst4[i];
            int ss[4] = {s4.x, s4.y, s4.z, s4.w};
            int dd[4] = {d4.x, d4.y, d4.z, d4.w};
            #pragma unroll
            for (int k = 0; k < 4; k++) {
                int s = ((unsigned)ss[k] < (unsigned)N) ? ss[k] : 0;
                int d = ((unsigned)dd[k] < (unsigned)N) ? dd[k] : 0;
                float v = gv_asrc[s] + gv_adst[d];
                v = (v > 0.0f) ? v : NEG_SLOPE * v;
                float ex = __expf(v);
                atomicAdd(&gv_denom[d], ex);
                int p = gv_off[d] + atomicAdd(&gv_cnt[d], 1);
                gv_se[p] = make_int2(s, __float_as_int(ex));
            }
        }
        for (int i = (E4 << 2) + blockIdx.x * blockDim.x + threadIdx.x; i < E;
             i += gridDim.x * blockDim.x) {
            int s = ei[i], d = ei[E + i];
            s = ((unsigned)s < (unsigned)N) ? s : 0;
            d = ((unsigned)d < (unsigned)N) ? d : 0;
            float v = gv_asrc[s] + gv_adst[d];
            v = (v > 0.0f) ? v : NEG_SLOPE * v;
            float ex = __expf(v);
            atomicAdd(&gv_denom[d], ex);
            int p = gv_off[d] + atomicAdd(&gv_cnt[d], 1);
            gv_se[p] = make_int2(s, __float_as_int(ex));
        }
    } else {
        const long long* el = (const long long*)ei;
        for (int i = blockIdx.x * blockDim.x + threadIdx.x; i < E;
             i += gridDim.x * blockDim.x) {
            int s = (int)el[i], d = (int)el[E + i];
            s = ((unsigned)s < (unsigned)N) ? s : 0;
            d = ((unsigned)d < (unsigned)N) ? d : 0;
            float v = gv_asrc[s] + gv_adst[d];
            v = (v > 0.0f) ? v : NEG_SLOPE * v;
            float ex = __expf(v);
            atomicAdd(&gv_denom[d], ex);
            int p = gv_off[d] + atomicAdd(&gv_cnt[d], 1);
            gv_se[p] = make_int2(s, __float_as_int(ex));
        }
    }
}

// 6) gather: one warp per dst; weighted fp16 row gather + tanh(+bias) -> out
__global__ __launch_bounds__(256) void kh_gather(
    float* __restrict__ out, const float* __restrict__ bias, int N)
{
    int warp = (blockIdx.x * blockDim.x + threadIdx.x) >> 5;
    int lane = threadIdx.x & 31;
    if (warp >= N) return;
    int beg = gv_off[warp];
    int end = beg + gv_cnt[warp];
    float inv = 1.0f / (gv_denom[warp] + EPS);

    float2 acc = make_float2(0.0f, 0.0f);
    int j = beg;
    if ((beg & 1) == 0) {
        for (; j + 1 < end; j += 2) {
            int4 p2 = *(const int4*)&gv_se[j];    // {s0,e0,s1,e1} broadcast
            float a0 = __int_as_float(p2.y) * inv;
            float a1 = __int_as_float(p2.w) * inv;
            float2 h0 = __half22float2(gv_h2[(size_t)p2.x * (C / 2) + lane]);
            float2 h1 = __half22float2(gv_h2[(size_t)p2.z * (C / 2) + lane]);
            acc.x = fmaf(a0, h0.x, acc.x);
            acc.y = fmaf(a0, h0.y, acc.y);
            acc.x = fmaf(a1, h1.x, acc.x);
            acc.y = fmaf(a1, h1.y, acc.y);
        }
    }
    for (; j < end; j++) {
        int2 se = gv_se[j];
        float a = __int_as_float(se.y) * inv;
        float2 hv = __half22float2(gv_h2[(size_t)se.x * (C / 2) + lane]);
        acc.x = fmaf(a, hv.x, acc.x);
        acc.y = fmaf(a, hv.y, acc.y);
    }
    float2 r;
    r.x = tanhf(acc.x + bias[lane * 2 + 0]);
    r.y = tanhf(acc.y + bias[lane * 2 + 1]);
    *(float2*)&out[(size_t)warp * C + lane * 2] = r;
}

extern "C" void kernel_launch(void* const* d_in, const int* in_sizes, int n_in,
                              void* d_out, int out_size)
{
    const float* x       = (const float*)d_in[0];
    const int*   ei      = (const int*)d_in[1];
    const float* W       = (const float*)d_in[2];
    const float* att_src = (const float*)d_in[3];
    const float* att_dst = (const float*)d_in[4];
    const float* bias    = (const float*)d_in[5];
    float* out = (float*)d_out;

    int N = in_sizes[0] / C;
    int E = in_sizes[1] / 2;

    int gridE4 = (E / 4 + 255) / 256;
    int gridN  = (N + 255) / 256;
    int NB = (N + SCHUNK - 1) / SCHUNK;

    kh_detect<<<1, 256>>>(ei);
    kh_zero<<<gridN, 256>>>(N);
    kh_hist<<<gridE4, 256>>>(ei, E, N);
    kh_scanA<<<NB, 256>>>(N);
    kh_scanB<<<1, 1024>>>(NB);
    kh_scanC<<<NB, 256>>>(N);
    kh_gemm<<<(N + 31) / 32, 256>>>(x, W, att_src, att_dst, N);
    kh_reorder<<<gridE4, 256>>>(ei, E, N);
    kh_gather<<<(N * 32 + 255) / 256, 256>>>(out, bias, N);
}

// round 15
// speedup vs baseline: 2.2237x; 1.1053x over previous
#include <cuda_runtime.h>
#include <cuda_fp16.h>
#include <cstdint>

#define N_MAX 100000
#define E_MAX 1600000
#define C 64
#define NEG_SLOPE 0.2f
#define EPS 1e-16f
#define SCHUNK 1024
#define HB 1024          // hist blocks co-launched with gemm

// Scratch (no device allocation allowed)
__device__ __half2 gx_h2[(size_t)N_MAX * (C / 2)];
__device__ float   gx_asrc[N_MAX];
__device__ float   gx_adst[N_MAX];
__device__ int2    gx_se[E_MAX];         // sorted-by-dst: {src, e_bits}
__device__ int     gx_cnt[N_MAX];        // degree histogram
__device__ int     gx_off[N_MAX];        // excl prefix; destroyed by reorder cursor
__device__ int     gx_bsum[128];
__device__ int     gx_is64;

// 1) detect dtype (block 0) + zero counts (all blocks)
__global__ void kp_init(const int* __restrict__ ei_raw, int N) {
    if (blockIdx.x == 0) {
        __shared__ int nz[256];
        int t = threadIdx.x;
        int acc = 0;
        for (int k = t; k < 2048; k += 256) acc |= ei_raw[2 * k + 1];
        nz[t] = acc;
        __syncthreads();
        for (int s = 128; s > 0; s >>= 1) {
            if (t < s) nz[t] |= nz[t + s];
            __syncthreads();
        }
        if (t == 0) gx_is64 = (nz[0] == 0) ? 1 : 0;
    }
    for (int i = blockIdx.x * blockDim.x + threadIdx.x; i < N;
         i += gridDim.x * blockDim.x)
        gx_cnt[i] = 0;
}

// 2) fused: blocks [0,HB) histogram dst; blocks [HB, HB+gemmBlocks) gemm tiles
__global__ __launch_bounds__(256) void kp_gemm_hist(
    const float* __restrict__ x, const float* __restrict__ W,
    const float* __restrict__ att_src, const float* __restrict__ att_dst,
    const int* __restrict__ ei, int E, int N)
{
    __shared__ float Ws[C * C];
    __shared__ float xs[32 * C];
    __shared__ float part[32][2][2];

    if (blockIdx.x < HB) {
        // ---- histogram role ----
        int is64 = gx_is64;
        int tid0 = blockIdx.x * blockDim.x + threadIdx.x;
        int stride = HB * blockDim.x;
        if (!is64) {
            const int4* dst4 = (const int4*)(ei + E);
            int E4 = E >> 2;
            for (int i = tid0; i < E4; i += stride) {
                int4 d4 = dst4[i];
                int d0 = ((unsigned)d4.x < (unsigned)N) ? d4.x : 0;
                int d1 = ((unsigned)d4.y < (unsigned)N) ? d4.y : 0;
                int d2 = ((unsigned)d4.z < (unsigned)N) ? d4.z : 0;
                int d3 = ((unsigned)d4.w < (unsigned)N) ? d4.w : 0;
                atomicAdd(&gx_cnt[d0], 1);
                atomicAdd(&gx_cnt[d1], 1);
                atomicAdd(&gx_cnt[d2], 1);
                atomicAdd(&gx_cnt[d3], 1);
            }
            for (int i = (E4 << 2) + tid0; i < E; i += stride) {
                int d = ei[E + i];
                d = ((unsigned)d < (unsigned)N) ? d : 0;
                atomicAdd(&gx_cnt[d], 1);
            }
        } else {
            const long long* el = (const long long*)ei;
            for (int i = tid0; i < E; i += stride) {
                int d = (int)el[E + i];
                d = ((unsigned)d < (unsigned)N) ? d : 0;
                atomicAdd(&gx_cnt[d], 1);
            }
        }
        return;
    }

    // ---- gemm role ----
    int gb = blockIdx.x - HB;
    int tid  = threadIdx.x;
    int lane = tid & 31;
    int half = (tid >> 5) & 1;
    int rq   = tid >> 6;
    int col  = half * 32 + lane;

    for (int i = tid; i < C * C; i += 256) Ws[i] = W[i];
    int row0 = gb * 32;
    int nrows = min(32, N - row0);
    if (nrows <= 0) return;
    for (int i = tid; i < nrows * C; i += 256) xs[i] = x[(size_t)row0 * C + i];
    __syncthreads();

    float as = att_src[col];
    float ad = att_dst[col];
    for (int r = rq; r < nrows; r += 4) {
        float acc = 0.0f;
        #pragma unroll
        for (int k = 0; k < C; k++)
            acc = fmaf(xs[r * C + k], Ws[k * C + col], acc);
        float nb = __shfl_down_sync(0xffffffffu, acc, 1);
        if ((lane & 1) == 0)
            gx_h2[(size_t)(row0 + r) * (C / 2) + (col >> 1)] =
                __floats2half2_rn(acc, nb);
        float ps = acc * as;
        float pd = acc * ad;
        #pragma unroll
        for (int off = 16; off > 0; off >>= 1) {
            ps += __shfl_down_sync(0xffffffffu, ps, off);
            pd += __shfl_down_sync(0xffffffffu, pd, off);
        }
        if (lane == 0) { part[r][half][0] = ps; part[r][half][1] = pd; }
    }
    __syncthreads();
    if (tid < nrows) {
        gx_asrc[row0 + tid] = part[tid][0][0] + part[tid][1][0];
        gx_adst[row0 + tid] = part[tid][0][1] + part[tid][1][1];
    }
}

// 3a) per-block sums of counts
__global__ __launch_bounds__(256) void kp_scanA(int N) {
    __shared__ int sh[256];
    int t = threadIdx.x;
    int base = blockIdx.x * SCHUNK + t * 4;
    int s = 0;
    #pragma unroll
    for (int k = 0; k < 4; k++) {
        int i = base + k;
        if (i < N) s += gx_cnt[i];
    }
    sh[t] = s;
    __syncthreads();
    for (int o = 128; o > 0; o >>= 1) {
        if (t < o) sh[t] += sh[t + o];
        __syncthreads();
    }
    if (t == 0) gx_bsum[blockIdx.x] = sh[0];
}

// 3b) fused scanB+C: every block scans the <=128 block sums in smem,
//     takes its exclusive prefix, then intra-block scans 1024 counts -> gx_off
__global__ __launch_bounds__(256) void kp_scanC(int N, int NB) {
    __shared__ int bs[128];
    __shared__ int sh[256];
    int t = threadIdx.x;
    if (t < 128) bs[t] = (t < NB) ? gx_bsum[t] : 0;
    __syncthreads();
    for (int o = 1; o < 128; o <<= 1) {
        int u = (t < 128 && t >= o) ? bs[t - o] : 0;
        __syncthreads();
        if (t < 128) bs[t] += u;
        __syncthreads();
    }
    int base0 = (blockIdx.x == 0) ? 0 : bs[blockIdx.x - 1];

    int base = blockIdx.x * SCHUNK + t * 4;
    int c[4];
    int s = 0;
    #pragma unroll
    for (int k = 0; k < 4; k++) {
        int i = base + k;
        c[k] = (i < N) ? gx_cnt[i] : 0;
        s += c[k];
    }
    sh[t] = s;
    __syncthreads();
    for (int o = 1; o < 256; o <<= 1) {
        int u = (t >= o) ? sh[t - o] : 0;
        __syncthreads();
        sh[t] += u;
        __syncthreads();
    }
    int excl = base0 + sh[t] - s;
    #pragma unroll
    for (int k = 0; k < 4; k++) {
        int i = base + k;
        if (i < N) {
            gx_off[i] = excl;
            excl += c[k];
        }
    }
}

// 4) reorder: logit -> exp, claim slot via destructive cursor on gx_off[d]
__global__ __launch_bounds__(256) void kp_reorder(
    const int* __restrict__ ei, int E, int N)
{
    int is64 = gx_is64;
    if (!is64) {
        const int4* src4 = (const int4*)ei;
        const int4* dst4 = (const int4*)(ei + E);
        int E4 = E >> 2;
        for (int i = blockIdx.x * blockDim.x + threadIdx.x; i < E4;
             i += gridDim.x * blockDim.x) {
            int4 s4 = src4[i];
            int4 d4 = dst4[i];
            int ss[4] = {s4.x, s4.y, s4.z, s4.w};
            int dd[4] = {d4.x, d4.y, d4.z, d4.w};
            #pragma unroll
            for (int k = 0; k < 4; k++) {
                int s = ((unsigned)ss[k] < (unsigned)N) ? ss[k] : 0;
                int d = ((unsigned)dd[k] < (unsigned)N) ? dd[k] : 0;
                float v = gx_asrc[s] + gx_adst[d];
                v = (v > 0.0f) ? v : NEG_SLOPE * v;
                float ex = __expf(v);
                int p = atomicAdd(&gx_off[d], 1);
                gx_se[p] = make_int2(s, __float_as_int(ex));
            }
        }
        for (int i = (E4 << 2) + blockIdx.x * blockDim.x + threadIdx.x; i < E;
             i += gridDim.x * blockDim.x) {
            int s = ei[i], d = ei[E + i];
            s = ((unsigned)s < (unsigned)N) ? s : 0;
            d = ((unsigned)d < (unsigned)N) ? d : 0;
            float v = gx_asrc[s] + gx_adst[d];
            v = (v > 0.0f) ? v : NEG_SLOPE * v;
            float ex = __expf(v);
            int p = atomicAdd(&gx_off[d], 1);
            gx_se[p] = make_int2(s, __float_as_int(ex));
        }
    } else {
        const long long* el = (const long long*)ei;
        for (int i = blockIdx.x * blockDim.x + threadIdx.x; i < E;
             i += gridDim.x * blockDim.x) {
            int s = (int)el[i], d = (int)el[E + i];
            s = ((unsigned)s < (unsigned)N) ? s : 0;
            d = ((unsigned)d < (unsigned)N) ? d : 0;
            float v = gx_asrc[s] + gx_adst[d];
            v = (v > 0.0f) ? v : NEG_SLOPE * v;
            float ex = __expf(v);
            int p = atomicAdd(&gx_off[d], 1);
            gx_se[p] = make_int2(s, __float_as_int(ex));
        }
    }
}

// 5) gather: one warp per dst; single loop accumulates numerator AND denom,
//    out = tanh((Σ e·h)/(Σ e + EPS) + bias).  Post-reorder segment of node d
//    is [off[d-1], off[d])  (off[d] was advanced by exactly deg[d]).
__global__ __launch_bounds__(256) void kp_gather(
    float* __restrict__ out, const float* __restrict__ bias, int N)
{
    int warp = (blockIdx.x * blockDim.x + threadIdx.x) >> 5;
    int lane = threadIdx.x & 31;
    if (warp >= N) return;
    int beg = (warp == 0) ? 0 : gx_off[warp - 1];
    int end = gx_off[warp];

    float ds = 0.0f;
    float2 acc = make_float2(0.0f, 0.0f);
    int j = beg;
    if ((beg & 1) == 0) {
        for (; j + 1 < end; j += 2) {
            int4 p2 = *(const int4*)&gx_se[j];   // {s0,e0,s1,e1} broadcast
            float e0 = __int_as_float(p2.y);
            float e1 = __int_as_float(p2.w);
            ds += e0 + e1;
            float2 h0 = __half22float2(gx_h2[(size_t)p2.x * (C / 2) + lane]);
            float2 h1 = __half22float2(gx_h2[(size_t)p2.z * (C / 2) + lane]);
            acc.x = fmaf(e0, h0.x, acc.x);
            acc.y = fmaf(e0, h0.y, acc.y);
            acc.x = fmaf(e1, h1.x, acc.x);
            acc.y = fmaf(e1, h1.y, acc.y);
        }
    }
    for (; j < end; j++) {
        int2 se = gx_se[j];
        float e = __int_as_float(se.y);
        ds += e;
        float2 hv = __half22float2(gx_h2[(size_t)se.x * (C / 2) + lane]);
        acc.x = fmaf(e, hv.x, acc.x);
        acc.y = fmaf(e, hv.y, acc.y);
    }
    float inv = 1.0f / (ds + EPS);
    float2 r;
    r.x = tanhf(fmaf(acc.x, inv, bias[lane * 2 + 0]));
    r.y = tanhf(fmaf(acc.y, inv, bias[lane * 2 + 1]));
    *(float2*)&out[(size_t)warp * C + lane * 2] = r;
}

extern "C" void kernel_launch(void* const* d_in, const int* in_sizes, int n_in,
                              void* d_out, int out_size)
{
    const float* x       = (const float*)d_in[0];
    const int*   ei      = (const int*)d_in[1];
    const float* W       = (const float*)d_in[2];
    const float* att_src = (const float*)d_in[3];
    const float* att_dst = (const float*)d_in[4];
    const float* bias    = (const float*)d_in[5];
    float* out = (float*)d_out;

    int N = in_sizes[0] / C;
    int E = in_sizes[1] / 2;

    int gridN  = (N + 255) / 256;
    int gemmB  = (N + 31) / 32;
    int gridE4 = (E / 4 + 255) / 256;
    int NB = (N + SCHUNK - 1) / SCHUNK;

    kp_init<<<gridN, 256>>>(ei, N);
    kp_gemm_hist<<<HB + gemmB, 256>>>(x, W, att_src, att_dst, ei, E, N);
    kp_scanA<<<NB, 256>>>(N);
    kp_scanC<<<NB, 256>>>(N, NB);
    kp_reorder<<<gridE4, 256>>>(ei, E, N);
    kp_gather<<<(N * 32 + 255) / 256, 256>>>(out, bias, N);
}